// round 9
// baseline (speedup 1.0000x reference)
#include <cuda_runtime.h>
#include <cuda_bf16.h>
#include <math.h>
#include <stdint.h>

#define D      256
#define N1C    40000
#define N2C    8000
#define E1MAX  1000000
#define KEXP   1536          // expanded K:  [Ah|Ah|Al] x [Wh;Wl;Wh]
#define KSTORE 1024          // Aexp stored dedup'd: [Ah|Al]
#define BM     128
#define BN     128
#define KC     64
#define NCHUNK 24            // 1536/64
#define STAGES 3
#define STAGE_BYTES (BM*128 + BN*128)
#define SMEM_BYTES  (STAGES*STAGE_BYTES + 1024)

// ---------------- scratch ----------------
__device__ float g_h1[(size_t)N1C * D];
__device__ __nv_bfloat16 g_Aexp[(size_t)N1C * KSTORE];   // 81.9 MB (reused layer 2)
__device__ __nv_bfloat16 g_Wb1[(size_t)D * KEXP];
__device__ __nv_bfloat16 g_Wb2[(size_t)D * KEXP];
__device__ int g_hist[N1C];
__device__ int g_off[N1C + 1];
__device__ int g_cur[N1C];
__device__ int g_ssrc[E1MAX];

// ---------------- helpers ----------------
__device__ __forceinline__ uint32_t smem_u32(const void* p) {
    uint32_t a;
    asm("{ .reg .u64 t; cvta.to.shared.u64 t, %1; cvt.u32.u64 %0, t; }"
        : "=r"(a) : "l"(p));
    return a;
}
#define SWZ(o) ((o) ^ (((o) >> 3) & 0x70))

__device__ __forceinline__ void cp_async16(uint32_t dst, const void* src) {
    asm volatile("cp.async.cg.shared.global [%0], [%1], 16;" :: "r"(dst), "l"(src));
}
#define CP_COMMIT()  asm volatile("cp.async.commit_group;")
#define CP_WAIT(n)   asm volatile("cp.async.wait_group %0;" :: "n"(n))

__device__ __forceinline__ void ldsm_x4(uint32_t& r0, uint32_t& r1,
                                        uint32_t& r2, uint32_t& r3, uint32_t addr) {
    asm volatile("ldmatrix.sync.aligned.m8n8.x4.shared.b16 {%0,%1,%2,%3}, [%4];"
                 : "=r"(r0), "=r"(r1), "=r"(r2), "=r"(r3) : "r"(addr));
}
__device__ __forceinline__ void mma_bf16(float* c,
        uint32_t a0, uint32_t a1, uint32_t a2, uint32_t a3,
        uint32_t b0, uint32_t b1) {
    asm volatile(
        "mma.sync.aligned.m16n8k16.row.col.f32.bf16.bf16.f32 "
        "{%0,%1,%2,%3}, {%4,%5,%6,%7}, {%8,%9}, {%0,%1,%2,%3};"
        : "+f"(c[0]), "+f"(c[1]), "+f"(c[2]), "+f"(c[3])
        : "r"(a0), "r"(a1), "r"(a2), "r"(a3), "r"(b0), "r"(b1));
}

// ---------------- sort-by-dst pipeline ----------------
__global__ void hist_kernel(const int* __restrict__ dst, int E, int* __restrict__ hist) {
    int i = blockIdx.x * blockDim.x + threadIdx.x;
    if (i < E) atomicAdd(hist + dst[i], 1);
}

__global__ void scan_kernel(const int* __restrict__ hist, int* __restrict__ off,
                            int* __restrict__ cur, int n, int E) {
    __shared__ int part[1024];
    const int t = threadIdx.x;
    const int chunk = (n + 1023) / 1024;
    int b0 = t * chunk;
    int b1 = b0 + chunk; if (b1 > n) b1 = n;
    if (b0 > n) b0 = n;
    int s = 0;
    for (int i = b0; i < b1; i++) s += hist[i];
    part[t] = s;
    __syncthreads();
    #pragma unroll
    for (int d = 1; d < 1024; d <<= 1) {
        int v = (t >= d) ? part[t - d] : 0;
        __syncthreads();
        part[t] += v;
        __syncthreads();
    }
    int run = (t > 0) ? part[t - 1] : 0;
    for (int i = b0; i < b1; i++) {
        off[i] = run;
        cur[i] = run;
        run += hist[i];
    }
    if (t == 0) off[n] = E;
}

__global__ void bin_kernel(const int* __restrict__ src, const int* __restrict__ dst,
                           int E, int* __restrict__ cur, int* __restrict__ ssrc) {
    int i = blockIdx.x * blockDim.x + threadIdx.x;
    if (i >= E) return;
    int p = atomicAdd(cur + dst[i], 1);
    ssrc[p] = src[i];
}

// ---------------- fused aggregation + mean + bf16-split prep ----------------
// warp per dst node: mean over segment, load x_tgt row, write Aexp row:
// [0:256)=hi(mean) [256:512)=hi(x) [512:768)=lo(mean) [768:1024)=lo(x)
__device__ __forceinline__ void split4(float4 v, ushort4& hi, ushort4& lo) {
    float f[4] = {v.x, v.y, v.z, v.w};
    unsigned short* hp = &hi.x;
    unsigned short* lp = &lo.x;
    #pragma unroll
    for (int t = 0; t < 4; t++) {
        __nv_bfloat16 h = __float2bfloat16(f[t]);
        __nv_bfloat16 l = __float2bfloat16(f[t] - __bfloat162float(h));
        hp[t] = *(unsigned short*)&h;
        lp[t] = *(unsigned short*)&l;
    }
}
__device__ __forceinline__ void acc4(float4& a, float4 v) {
    a.x += v.x; a.y += v.y; a.z += v.z; a.w += v.w;
}

__global__ void agg_prep_kernel(const float* __restrict__ x,
                                const int* __restrict__ off,
                                const int* __restrict__ ssrc,
                                __nv_bfloat16* __restrict__ Aexp, int n) {
    const int d = (blockIdx.x * blockDim.x + threadIdx.x) >> 5;
    const int lane = threadIdx.x & 31;
    if (d >= n) return;
    const int beg = __ldg(off + d);
    const int end = __ldg(off + d + 1);

    float4 a0 = make_float4(0, 0, 0, 0), a1 = make_float4(0, 0, 0, 0);
    int e = beg;
    // 4-edge unroll: 8 outstanding LDG.128 per lane
    for (; e + 4 <= end; e += 4) {
        int s0 = __ldg(ssrc + e + 0);
        int s1 = __ldg(ssrc + e + 1);
        int s2 = __ldg(ssrc + e + 2);
        int s3 = __ldg(ssrc + e + 3);
        const float4* p0 = (const float4*)(x + (size_t)s0 * D);
        const float4* p1 = (const float4*)(x + (size_t)s1 * D);
        const float4* p2 = (const float4*)(x + (size_t)s2 * D);
        const float4* p3 = (const float4*)(x + (size_t)s3 * D);
        float4 u00 = __ldg(p0 + lane),      u01 = __ldg(p0 + lane + 32);
        float4 u10 = __ldg(p1 + lane),      u11 = __ldg(p1 + lane + 32);
        float4 u20 = __ldg(p2 + lane),      u21 = __ldg(p2 + lane + 32);
        float4 u30 = __ldg(p3 + lane),      u31 = __ldg(p3 + lane + 32);
        acc4(a0, u00); acc4(a1, u01);
        acc4(a0, u10); acc4(a1, u11);
        acc4(a0, u20); acc4(a1, u21);
        acc4(a0, u30); acc4(a1, u31);
    }
    for (; e < end; e++) {
        int s = __ldg(ssrc + e);
        const float4* p = (const float4*)(x + (size_t)s * D);
        acc4(a0, __ldg(p + lane));
        acc4(a1, __ldg(p + lane + 32));
    }

    const float inv = 1.0f / fmaxf((float)(end - beg), 1.0f);
    a0.x *= inv; a0.y *= inv; a0.z *= inv; a0.w *= inv;
    a1.x *= inv; a1.y *= inv; a1.z *= inv; a1.w *= inv;

    // x_tgt row (same table: x_tgt = x[:n])
    const float4* pt = (const float4*)(x + (size_t)d * D);
    float4 t0 = __ldg(pt + lane), t1 = __ldg(pt + lane + 32);

    ushort4 h, l;
    __nv_bfloat16* row = Aexp + (size_t)d * KSTORE;
    split4(a0, h, l);
    *(ushort4*)(row +   0 + 4 * lane) = h;  *(ushort4*)(row + 512 + 4 * lane) = l;
    split4(a1, h, l);
    *(ushort4*)(row + 128 + 4 * lane) = h;  *(ushort4*)(row + 640 + 4 * lane) = l;
    split4(t0, h, l);
    *(ushort4*)(row + 256 + 4 * lane) = h;  *(ushort4*)(row + 768 + 4 * lane) = l;
    split4(t1, h, l);
    *(ushort4*)(row + 384 + 4 * lane) = h;  *(ushort4*)(row + 896 + 4 * lane) = l;
}

// ---------------- weight prep ----------------
__global__ void wprep_kernel(const float* __restrict__ Wl, const float* __restrict__ Wr,
                             __nv_bfloat16* __restrict__ Wb) {
    int i = blockIdx.x * blockDim.x + threadIdx.x;
    if (i >= D * 512) return;
    int n = i / 512, k = i % 512;
    float w = (k < D) ? Wl[n * D + k] : Wr[n * D + (k - D)];
    __nv_bfloat16 hi = __float2bfloat16(w);
    __nv_bfloat16 lo = __float2bfloat16(w - __bfloat162float(hi));
    __nv_bfloat16* row = Wb + (size_t)n * KEXP;
    row[k]        = hi;
    row[512 + k]  = lo;
    row[1024 + k] = hi;
}

// ---------------- mma.sync bf16 GEMM (R7-proven, unchanged) ----------------
__global__ __launch_bounds__(256, 1)
void sage_mma_gemm(const __nv_bfloat16* __restrict__ Aexp,
                   const __nv_bfloat16* __restrict__ Wb,
                   const float* __restrict__ bias,
                   float* __restrict__ out, int M) {
    extern __shared__ __align__(1024) char smem[];
    const uint32_t TILES = (smem_u32(smem) + 1023u) & ~1023u;

    const int tid  = threadIdx.x;
    const int wid  = tid >> 5;
    const int lane = tid & 31;
    const int wm   = wid & 3;
    const int wn   = wid >> 2;
    const int row0 = blockIdx.x * BM;
    const int col0 = blockIdx.y * BN;

    const int ld_r = tid >> 3;
    const int ld_q = tid & 7;

    uint32_t aPart[2], bPart[4];
    {
        int r  = (lane & 15);
        int hb = (lane >> 4) * 16;
        #pragma unroll
        for (int mi = 0; mi < 2; mi++)
            aPart[mi] = (uint32_t)((wm * 32 + mi * 16 + r) * 128 + hb);
        #pragma unroll
        for (int g = 0; g < 4; g++)
            bPart[g] = (uint32_t)((wn * 64 + g * 16 + r) * 128 + hb);
    }

    float acc[2][8][4];
    #pragma unroll
    for (int mi = 0; mi < 2; mi++)
        #pragma unroll
        for (int ni = 0; ni < 8; ni++)
            #pragma unroll
            for (int t = 0; t < 4; t++) acc[mi][ni][t] = 0.0f;

    auto load_chunk = [&](int c) {
        const int s  = c % STAGES;
        const int kb = c * KC;
        const int ka = (kb < 512) ? kb : kb - 512;
        const uint32_t sA = TILES + s * STAGE_BYTES;
        const uint32_t sB = sA + BM * 128;
        #pragma unroll
        for (int i = 0; i < 4; i++) {
            int m = ld_r + i * 32;
            int gr = row0 + m; if (gr > M - 1) gr = M - 1;
            cp_async16(sA + SWZ(m * 128 + ld_q * 16),
                       Aexp + (size_t)gr * KSTORE + ka + ld_q * 8);
        }
        #pragma unroll
        for (int i = 0; i < 4; i++) {
            int n = ld_r + i * 32;
            cp_async16(sB + SWZ(n * 128 + ld_q * 16),
                       Wb + (size_t)(col0 + n) * KEXP + kb + ld_q * 8);
        }
        CP_COMMIT();
    };

    load_chunk(0);
    load_chunk(1);

    #pragma unroll 1
    for (int c = 0; c < NCHUNK; c++) {
        if (c == NCHUNK - 1) { CP_WAIT(0); } else { CP_WAIT(1); }
        __syncthreads();
        if (c + 2 < NCHUNK) load_chunk(c + 2);

        const uint32_t sA = TILES + (c % STAGES) * STAGE_BYTES;
        const uint32_t sB = sA + BM * 128;

        #pragma unroll
        for (int ks = 0; ks < 4; ks++) {
            const uint32_t kadv = ks * 32;
            uint32_t a[2][4];
            #pragma unroll
            for (int mi = 0; mi < 2; mi++)
                ldsm_x4(a[mi][0], a[mi][1], a[mi][2], a[mi][3],
                        sA + SWZ(aPart[mi] + kadv));
            uint32_t b[8][2];
            #pragma unroll
            for (int g = 0; g < 4; g++) {
                uint32_t r0, r1, r2, r3;
                ldsm_x4(r0, r1, r2, r3, sB + SWZ(bPart[g] + kadv));
                b[2*g][0] = r0;  b[2*g+1][0] = r1;
                b[2*g][1] = r2;  b[2*g+1][1] = r3;
            }
            #pragma unroll
            for (int mi = 0; mi < 2; mi++)
                #pragma unroll
                for (int ni = 0; ni < 8; ni++)
                    mma_bf16(acc[mi][ni],
                             a[mi][0], a[mi][1], a[mi][2], a[mi][3],
                             b[ni][0], b[ni][1]);
        }
    }

    const int rbase = row0 + wm * 32 + (lane >> 2);
    const int cbase = col0 + wn * 64 + 2 * (lane & 3);
    #pragma unroll
    for (int ni = 0; ni < 8; ni++) {
        const int col = cbase + ni * 8;
        const float2 bv = *(const float2*)(bias + col);
        #pragma unroll
        for (int mi = 0; mi < 2; mi++) {
            int r = rbase + mi * 16;
            if (r < M) {
                float2 o;
                o.x = tanhf(acc[mi][ni][0] + bv.x);
                o.y = tanhf(acc[mi][ni][1] + bv.y);
                *(float2*)(out + (size_t)r * D + col) = o;
            }
            if (r + 8 < M) {
                float2 o;
                o.x = tanhf(acc[mi][ni][2] + bv.x);
                o.y = tanhf(acc[mi][ni][3] + bv.y);
                *(float2*)(out + (size_t)(r + 8) * D + col) = o;
            }
        }
    }
}

// ---------------- launch ----------------
extern "C" void kernel_launch(void* const* d_in, const int* in_sizes, int n_in,
                              void* d_out, int out_size) {
    const float* nodes = (const float*)d_in[0];
    const float* Wl1   = (const float*)d_in[1];
    const float* b1    = (const float*)d_in[2];
    const float* Wr1   = (const float*)d_in[3];
    const float* Wl2   = (const float*)d_in[4];
    const float* b2    = (const float*)d_in[5];
    const float* Wr2   = (const float*)d_in[6];
    const int*   src1  = (const int*)d_in[7];
    const int*   dst1  = (const int*)d_in[8];
    const int*   src2  = (const int*)d_in[9];
    const int*   dst2  = (const int*)d_in[10];
    const int E1 = in_sizes[7];
    const int E2 = in_sizes[9];

    float *p_h1;
    __nv_bfloat16 *p_Aexp, *p_Wb1, *p_Wb2;
    int *p_hist, *p_off, *p_cur, *p_ssrc;
    cudaGetSymbolAddress((void**)&p_h1,   g_h1);
    cudaGetSymbolAddress((void**)&p_Aexp, g_Aexp);
    cudaGetSymbolAddress((void**)&p_Wb1,  g_Wb1);
    cudaGetSymbolAddress((void**)&p_Wb2,  g_Wb2);
    cudaGetSymbolAddress((void**)&p_hist, g_hist);
    cudaGetSymbolAddress((void**)&p_off,  g_off);
    cudaGetSymbolAddress((void**)&p_cur,  g_cur);
    cudaGetSymbolAddress((void**)&p_ssrc, g_ssrc);

    cudaFuncSetAttribute(sage_mma_gemm, cudaFuncAttributeMaxDynamicSharedMemorySize,
                         SMEM_BYTES);

    wprep_kernel<<<(D * 512 + 255) / 256, 256>>>(Wl1, Wr1, p_Wb1);
    wprep_kernel<<<(D * 512 + 255) / 256, 256>>>(Wl2, Wr2, p_Wb2);

    // ---- layer 1 ----
    cudaMemsetAsync(p_hist, 0, sizeof(int) * N1C);
    hist_kernel<<<(E1 + 255) / 256, 256>>>(dst1, E1, p_hist);
    scan_kernel<<<1, 1024>>>(p_hist, p_off, p_cur, N1C, E1);
    bin_kernel<<<(E1 + 255) / 256, 256>>>(src1, dst1, E1, p_cur, p_ssrc);
    agg_prep_kernel<<<(N1C * 32 + 255) / 256, 256>>>(nodes, p_off, p_ssrc, p_Aexp, N1C);
    {
        dim3 grid((N1C + BM - 1) / BM, D / BN);
        sage_mma_gemm<<<grid, 256, SMEM_BYTES>>>(p_Aexp, p_Wb1, b1, p_h1, N1C);
    }

    // ---- layer 2 ----
    cudaMemsetAsync(p_hist, 0, sizeof(int) * N2C);
    hist_kernel<<<(E2 + 255) / 256, 256>>>(dst2, E2, p_hist);
    scan_kernel<<<1, 1024>>>(p_hist, p_off, p_cur, N2C, E2);
    bin_kernel<<<(E2 + 255) / 256, 256>>>(src2, dst2, E2, p_cur, p_ssrc);
    agg_prep_kernel<<<(N2C * 32 + 255) / 256, 256>>>(p_h1, p_off, p_ssrc, p_Aexp, N2C);
    {
        dim3 grid((N2C + BM - 1) / BM, D / BN);
        sage_mma_gemm<<<grid, 256, SMEM_BYTES>>>(p_Aexp, p_Wb2, b2, (float*)d_out, N2C);
    }
}

// round 10
// speedup vs baseline: 1.1724x; 1.1724x over previous
#include <cuda_runtime.h>
#include <cuda_bf16.h>
#include <math.h>
#include <stdint.h>

#define D      256
#define N1C    40000
#define N2C    8000
#define E1MAX  1000000
#define KEXP   1536          // expanded K:  [Ah|Ah|Al] x [Wh;Wl;Wh]
#define KSTORE 1024          // Aexp stored dedup'd: [Ah|Al]
#define BM     128
#define BN     128
#define KC     64
#define NCHUNK 24            // 1536/64
#define STAGES 3
#define STAGE_BYTES (BM*128 + BN*128)
#define SMEM_BYTES  (STAGES*STAGE_BYTES + 1024)
#define SCAN_BLK 256
#define NBLK_MAX ((N1C + SCAN_BLK - 1) / SCAN_BLK)   // 157

// ---------------- scratch ----------------
__device__ float g_h1[(size_t)N1C * D];
__device__ __nv_bfloat16 g_Aexp[(size_t)N1C * KSTORE];   // 81.9 MB (reused layer 2)
__device__ __nv_bfloat16 g_Wb1[(size_t)D * KEXP];
__device__ __nv_bfloat16 g_Wb2[(size_t)D * KEXP];
__device__ int g_hist[N1C];
__device__ int g_off[N1C + 1];
__device__ int g_cur[N1C];
__device__ int g_ssrc[E1MAX];
__device__ int g_bsum[NBLK_MAX];

// ---------------- helpers ----------------
__device__ __forceinline__ uint32_t smem_u32(const void* p) {
    uint32_t a;
    asm("{ .reg .u64 t; cvta.to.shared.u64 t, %1; cvt.u32.u64 %0, t; }"
        : "=r"(a) : "l"(p));
    return a;
}
#define SWZ(o) ((o) ^ (((o) >> 3) & 0x70))

__device__ __forceinline__ void cp_async16(uint32_t dst, const void* src) {
    asm volatile("cp.async.cg.shared.global [%0], [%1], 16;" :: "r"(dst), "l"(src));
}
#define CP_COMMIT()  asm volatile("cp.async.commit_group;")
#define CP_WAIT(n)   asm volatile("cp.async.wait_group %0;" :: "n"(n))

__device__ __forceinline__ void ldsm_x4(uint32_t& r0, uint32_t& r1,
                                        uint32_t& r2, uint32_t& r3, uint32_t addr) {
    asm volatile("ldmatrix.sync.aligned.m8n8.x4.shared.b16 {%0,%1,%2,%3}, [%4];"
                 : "=r"(r0), "=r"(r1), "=r"(r2), "=r"(r3) : "r"(addr));
}
__device__ __forceinline__ void mma_bf16(float* c,
        uint32_t a0, uint32_t a1, uint32_t a2, uint32_t a3,
        uint32_t b0, uint32_t b1) {
    asm volatile(
        "mma.sync.aligned.m16n8k16.row.col.f32.bf16.bf16.f32 "
        "{%0,%1,%2,%3}, {%4,%5,%6,%7}, {%8,%9}, {%0,%1,%2,%3};"
        : "+f"(c[0]), "+f"(c[1]), "+f"(c[2]), "+f"(c[3])
        : "r"(a0), "r"(a1), "r"(a2), "r"(a3), "r"(b0), "r"(b1));
}

// ---------------- sort-by-dst pipeline ----------------
__global__ void hist_kernel(const int* __restrict__ dst, int E, int* __restrict__ hist) {
    int i = blockIdx.x * blockDim.x + threadIdx.x;
    if (i < E) atomicAdd(hist + dst[i], 1);
}

// 3-kernel parallel scan: partial sums -> scan of block sums -> offsets
__global__ void partial_kernel(const int* __restrict__ hist, int* __restrict__ bsum, int n) {
    __shared__ int sh[SCAN_BLK];
    int i = blockIdx.x * SCAN_BLK + threadIdx.x;
    sh[threadIdx.x] = (i < n) ? hist[i] : 0;
    __syncthreads();
    #pragma unroll
    for (int d = SCAN_BLK / 2; d > 0; d >>= 1) {
        if (threadIdx.x < d) sh[threadIdx.x] += sh[threadIdx.x + d];
        __syncthreads();
    }
    if (threadIdx.x == 0) bsum[blockIdx.x] = sh[0];
}

__global__ void bscan_kernel(int* __restrict__ bsum, int nb) {
    __shared__ int sh[1024];
    int t = threadIdx.x;
    int v = (t < nb) ? bsum[t] : 0;
    sh[t] = v;
    __syncthreads();
    #pragma unroll
    for (int d = 1; d < 1024; d <<= 1) {
        int u = (t >= d) ? sh[t - d] : 0;
        __syncthreads();
        sh[t] += u;
        __syncthreads();
    }
    if (t < nb) bsum[t] = sh[t] - v;    // exclusive
}

__global__ void offsets_kernel(const int* __restrict__ hist, const int* __restrict__ bsum,
                               int* __restrict__ off, int* __restrict__ cur,
                               int n, int E) {
    __shared__ int sh[SCAN_BLK];
    int i = blockIdx.x * SCAN_BLK + threadIdx.x;
    int v = (i < n) ? hist[i] : 0;
    sh[threadIdx.x] = v;
    __syncthreads();
    #pragma unroll
    for (int d = 1; d < SCAN_BLK; d <<= 1) {
        int u = (threadIdx.x >= d) ? sh[threadIdx.x - d] : 0;
        __syncthreads();
        sh[threadIdx.x] += u;
        __syncthreads();
    }
    int o = bsum[blockIdx.x] + sh[threadIdx.x] - v;   // exclusive prefix
    if (i < n) { off[i] = o; cur[i] = o; }
    if (i == 0 && blockIdx.x == 0) off[n] = E;
}

__global__ void bin_kernel(const int* __restrict__ src, const int* __restrict__ dst,
                           int E, int* __restrict__ cur, int* __restrict__ ssrc) {
    int i = blockIdx.x * blockDim.x + threadIdx.x;
    if (i >= E) return;
    int p = atomicAdd(cur + dst[i], 1);
    ssrc[p] = src[i];
}

// ---------------- fused aggregation + mean + bf16-split prep ----------------
// warp per dst node; Aexp row: [0:256)=hi(mean) [256:512)=hi(x) [512:768)=lo(mean) [768:1024)=lo(x)
__device__ __forceinline__ void split4(float4 v, ushort4& hi, ushort4& lo) {
    float f[4] = {v.x, v.y, v.z, v.w};
    unsigned short* hp = &hi.x;
    unsigned short* lp = &lo.x;
    #pragma unroll
    for (int t = 0; t < 4; t++) {
        __nv_bfloat16 h = __float2bfloat16(f[t]);
        __nv_bfloat16 l = __float2bfloat16(f[t] - __bfloat162float(h));
        hp[t] = *(unsigned short*)&h;
        lp[t] = *(unsigned short*)&l;
    }
}
__device__ __forceinline__ void acc4(float4& a, float4 v) {
    a.x += v.x; a.y += v.y; a.z += v.z; a.w += v.w;
}

__global__ void agg_prep_kernel(const float* __restrict__ x,
                                const int* __restrict__ off,
                                const int* __restrict__ ssrc,
                                __nv_bfloat16* __restrict__ Aexp, int n) {
    const int d = (blockIdx.x * blockDim.x + threadIdx.x) >> 5;
    const int lane = threadIdx.x & 31;
    if (d >= n) return;
    const int beg = __ldg(off + d);
    const int end = __ldg(off + d + 1);

    float4 a0 = make_float4(0, 0, 0, 0), a1 = make_float4(0, 0, 0, 0);
    int e = beg;
    for (; e + 4 <= end; e += 4) {
        int s0 = __ldg(ssrc + e + 0);
        int s1 = __ldg(ssrc + e + 1);
        int s2 = __ldg(ssrc + e + 2);
        int s3 = __ldg(ssrc + e + 3);
        const float4* p0 = (const float4*)(x + (size_t)s0 * D);
        const float4* p1 = (const float4*)(x + (size_t)s1 * D);
        const float4* p2 = (const float4*)(x + (size_t)s2 * D);
        const float4* p3 = (const float4*)(x + (size_t)s3 * D);
        float4 u00 = __ldg(p0 + lane),      u01 = __ldg(p0 + lane + 32);
        float4 u10 = __ldg(p1 + lane),      u11 = __ldg(p1 + lane + 32);
        float4 u20 = __ldg(p2 + lane),      u21 = __ldg(p2 + lane + 32);
        float4 u30 = __ldg(p3 + lane),      u31 = __ldg(p3 + lane + 32);
        acc4(a0, u00); acc4(a1, u01);
        acc4(a0, u10); acc4(a1, u11);
        acc4(a0, u20); acc4(a1, u21);
        acc4(a0, u30); acc4(a1, u31);
    }
    for (; e < end; e++) {
        int s = __ldg(ssrc + e);
        const float4* p = (const float4*)(x + (size_t)s * D);
        acc4(a0, __ldg(p + lane));
        acc4(a1, __ldg(p + lane + 32));
    }

    const float inv = 1.0f / fmaxf((float)(end - beg), 1.0f);
    a0.x *= inv; a0.y *= inv; a0.z *= inv; a0.w *= inv;
    a1.x *= inv; a1.y *= inv; a1.z *= inv; a1.w *= inv;

    const float4* pt = (const float4*)(x + (size_t)d * D);
    float4 t0 = __ldg(pt + lane), t1 = __ldg(pt + lane + 32);

    ushort4 h, l;
    __nv_bfloat16* row = Aexp + (size_t)d * KSTORE;
    split4(a0, h, l);
    *(ushort4*)(row +   0 + 4 * lane) = h;  *(ushort4*)(row + 512 + 4 * lane) = l;
    split4(a1, h, l);
    *(ushort4*)(row + 128 + 4 * lane) = h;  *(ushort4*)(row + 640 + 4 * lane) = l;
    split4(t0, h, l);
    *(ushort4*)(row + 256 + 4 * lane) = h;  *(ushort4*)(row + 768 + 4 * lane) = l;
    split4(t1, h, l);
    *(ushort4*)(row + 384 + 4 * lane) = h;  *(ushort4*)(row + 896 + 4 * lane) = l;
}

// ---------------- weight prep ----------------
__global__ void wprep_kernel(const float* __restrict__ Wl, const float* __restrict__ Wr,
                             __nv_bfloat16* __restrict__ Wb) {
    int i = blockIdx.x * blockDim.x + threadIdx.x;
    if (i >= D * 512) return;
    int n = i / 512, k = i % 512;
    float w = (k < D) ? Wl[n * D + k] : Wr[n * D + (k - D)];
    __nv_bfloat16 hi = __float2bfloat16(w);
    __nv_bfloat16 lo = __float2bfloat16(w - __bfloat162float(hi));
    __nv_bfloat16* row = Wb + (size_t)n * KEXP;
    row[k]        = hi;
    row[512 + k]  = lo;
    row[1024 + k] = hi;
}

// ---------------- mma.sync bf16 GEMM (R7-proven, unchanged) ----------------
__global__ __launch_bounds__(256, 1)
void sage_mma_gemm(const __nv_bfloat16* __restrict__ Aexp,
                   const __nv_bfloat16* __restrict__ Wb,
                   const float* __restrict__ bias,
                   float* __restrict__ out, int M) {
    extern __shared__ __align__(1024) char smem[];
    const uint32_t TILES = (smem_u32(smem) + 1023u) & ~1023u;

    const int tid  = threadIdx.x;
    const int wid  = tid >> 5;
    const int lane = tid & 31;
    const int wm   = wid & 3;
    const int wn   = wid >> 2;
    const int row0 = blockIdx.x * BM;
    const int col0 = blockIdx.y * BN;

    const int ld_r = tid >> 3;
    const int ld_q = tid & 7;

    uint32_t aPart[2], bPart[4];
    {
        int r  = (lane & 15);
        int hb = (lane >> 4) * 16;
        #pragma unroll
        for (int mi = 0; mi < 2; mi++)
            aPart[mi] = (uint32_t)((wm * 32 + mi * 16 + r) * 128 + hb);
        #pragma unroll
        for (int g = 0; g < 4; g++)
            bPart[g] = (uint32_t)((wn * 64 + g * 16 + r) * 128 + hb);
    }

    float acc[2][8][4];
    #pragma unroll
    for (int mi = 0; mi < 2; mi++)
        #pragma unroll
        for (int ni = 0; ni < 8; ni++)
            #pragma unroll
            for (int t = 0; t < 4; t++) acc[mi][ni][t] = 0.0f;

    auto load_chunk = [&](int c) {
        const int s  = c % STAGES;
        const int kb = c * KC;
        const int ka = (kb < 512) ? kb : kb - 512;
        const uint32_t sA = TILES + s * STAGE_BYTES;
        const uint32_t sB = sA + BM * 128;
        #pragma unroll
        for (int i = 0; i < 4; i++) {
            int m = ld_r + i * 32;
            int gr = row0 + m; if (gr > M - 1) gr = M - 1;
            cp_async16(sA + SWZ(m * 128 + ld_q * 16),
                       Aexp + (size_t)gr * KSTORE + ka + ld_q * 8);
        }
        #pragma unroll
        for (int i = 0; i < 4; i++) {
            int n = ld_r + i * 32;
            cp_async16(sB + SWZ(n * 128 + ld_q * 16),
                       Wb + (size_t)(col0 + n) * KEXP + kb + ld_q * 8);
        }
        CP_COMMIT();
    };

    load_chunk(0);
    load_chunk(1);

    #pragma unroll 1
    for (int c = 0; c < NCHUNK; c++) {
        if (c == NCHUNK - 1) { CP_WAIT(0); } else { CP_WAIT(1); }
        __syncthreads();
        if (c + 2 < NCHUNK) load_chunk(c + 2);

        const uint32_t sA = TILES + (c % STAGES) * STAGE_BYTES;
        const uint32_t sB = sA + BM * 128;

        #pragma unroll
        for (int ks = 0; ks < 4; ks++) {
            const uint32_t kadv = ks * 32;
            uint32_t a[2][4];
            #pragma unroll
            for (int mi = 0; mi < 2; mi++)
                ldsm_x4(a[mi][0], a[mi][1], a[mi][2], a[mi][3],
                        sA + SWZ(aPart[mi] + kadv));
            uint32_t b[8][2];
            #pragma unroll
            for (int g = 0; g < 4; g++) {
                uint32_t r0, r1, r2, r3;
                ldsm_x4(r0, r1, r2, r3, sB + SWZ(bPart[g] + kadv));
                b[2*g][0] = r0;  b[2*g+1][0] = r1;
                b[2*g][1] = r2;  b[2*g+1][1] = r3;
            }
            #pragma unroll
            for (int mi = 0; mi < 2; mi++)
                #pragma unroll
                for (int ni = 0; ni < 8; ni++)
                    mma_bf16(acc[mi][ni],
                             a[mi][0], a[mi][1], a[mi][2], a[mi][3],
                             b[ni][0], b[ni][1]);
        }
    }

    const int rbase = row0 + wm * 32 + (lane >> 2);
    const int cbase = col0 + wn * 64 + 2 * (lane & 3);
    #pragma unroll
    for (int ni = 0; ni < 8; ni++) {
        const int col = cbase + ni * 8;
        const float2 bv = *(const float2*)(bias + col);
        #pragma unroll
        for (int mi = 0; mi < 2; mi++) {
            int r = rbase + mi * 16;
            if (r < M) {
                float2 o;
                o.x = tanhf(acc[mi][ni][0] + bv.x);
                o.y = tanhf(acc[mi][ni][1] + bv.y);
                *(float2*)(out + (size_t)r * D + col) = o;
            }
            if (r + 8 < M) {
                float2 o;
                o.x = tanhf(acc[mi][ni][2] + bv.x);
                o.y = tanhf(acc[mi][ni][3] + bv.y);
                *(float2*)(out + (size_t)(r + 8) * D + col) = o;
            }
        }
    }
}

// ---------------- launch ----------------
extern "C" void kernel_launch(void* const* d_in, const int* in_sizes, int n_in,
                              void* d_out, int out_size) {
    const float* nodes = (const float*)d_in[0];
    const float* Wl1   = (const float*)d_in[1];
    const float* b1    = (const float*)d_in[2];
    const float* Wr1   = (const float*)d_in[3];
    const float* Wl2   = (const float*)d_in[4];
    const float* b2    = (const float*)d_in[5];
    const float* Wr2   = (const float*)d_in[6];
    const int*   src1  = (const int*)d_in[7];
    const int*   dst1  = (const int*)d_in[8];
    const int*   src2  = (const int*)d_in[9];
    const int*   dst2  = (const int*)d_in[10];
    const int E1 = in_sizes[7];
    const int E2 = in_sizes[9];

    float *p_h1;
    __nv_bfloat16 *p_Aexp, *p_Wb1, *p_Wb2;
    int *p_hist, *p_off, *p_cur, *p_ssrc, *p_bsum;
    cudaGetSymbolAddress((void**)&p_h1,   g_h1);
    cudaGetSymbolAddress((void**)&p_Aexp, g_Aexp);
    cudaGetSymbolAddress((void**)&p_Wb1,  g_Wb1);
    cudaGetSymbolAddress((void**)&p_Wb2,  g_Wb2);
    cudaGetSymbolAddress((void**)&p_hist, g_hist);
    cudaGetSymbolAddress((void**)&p_off,  g_off);
    cudaGetSymbolAddress((void**)&p_cur,  g_cur);
    cudaGetSymbolAddress((void**)&p_ssrc, g_ssrc);
    cudaGetSymbolAddress((void**)&p_bsum, g_bsum);

    cudaFuncSetAttribute(sage_mma_gemm, cudaFuncAttributeMaxDynamicSharedMemorySize,
                         SMEM_BYTES);

    wprep_kernel<<<(D * 512 + 255) / 256, 256>>>(Wl1, Wr1, p_Wb1);
    wprep_kernel<<<(D * 512 + 255) / 256, 256>>>(Wl2, Wr2, p_Wb2);

    // ---- layer 1 ----
    {
        const int nb = (N1C + SCAN_BLK - 1) / SCAN_BLK;
        cudaMemsetAsync(p_hist, 0, sizeof(int) * N1C);
        hist_kernel<<<(E1 + 255) / 256, 256>>>(dst1, E1, p_hist);
        partial_kernel<<<nb, SCAN_BLK>>>(p_hist, p_bsum, N1C);
        bscan_kernel<<<1, 1024>>>(p_bsum, nb);
        offsets_kernel<<<nb, SCAN_BLK>>>(p_hist, p_bsum, p_off, p_cur, N1C, E1);
        bin_kernel<<<(E1 + 255) / 256, 256>>>(src1, dst1, E1, p_cur, p_ssrc);
        agg_prep_kernel<<<(N1C * 32 + 255) / 256, 256>>>(nodes, p_off, p_ssrc, p_Aexp, N1C);
        dim3 grid((N1C + BM - 1) / BM, D / BN);
        sage_mma_gemm<<<grid, 256, SMEM_BYTES>>>(p_Aexp, p_Wb1, b1, p_h1, N1C);
    }

    // ---- layer 2 ----
    {
        const int nb = (N2C + SCAN_BLK - 1) / SCAN_BLK;
        cudaMemsetAsync(p_hist, 0, sizeof(int) * N2C);
        hist_kernel<<<(E2 + 255) / 256, 256>>>(dst2, E2, p_hist);
        partial_kernel<<<nb, SCAN_BLK>>>(p_hist, p_bsum, N2C);
        bscan_kernel<<<1, 1024>>>(p_bsum, nb);
        offsets_kernel<<<nb, SCAN_BLK>>>(p_hist, p_bsum, p_off, p_cur, N2C, E2);
        bin_kernel<<<(E2 + 255) / 256, 256>>>(src2, dst2, E2, p_cur, p_ssrc);
        agg_prep_kernel<<<(N2C * 32 + 255) / 256, 256>>>(p_h1, p_off, p_ssrc, p_Aexp, N2C);
        dim3 grid((N2C + BM - 1) / BM, D / BN);
        sage_mma_gemm<<<grid, 256, SMEM_BYTES>>>(p_Aexp, p_Wb2, b2, (float*)d_out, N2C);
    }
}

// round 11
// speedup vs baseline: 1.2035x; 1.0265x over previous
#include <cuda_runtime.h>
#include <cuda_bf16.h>
#include <math.h>
#include <stdint.h>

#define D      256
#define N1C    40000
#define N2C    8000
#define E1MAX  1000000
#define KEXP   1536          // expanded K:  [Ah|Ah|Al] x [Wh;Wl;Wh]
#define KSTORE 1024          // Aexp stored dedup'd: [Ah|Al]
#define BM     128
#define BN     128
#define KC     64
#define NCHUNK 24            // 1536/64
#define STAGES 3
#define STAGE_BYTES (BM*128 + BN*128)
#define SMEM_BYTES  (STAGES*STAGE_BYTES + 1024)
#define SCAN_BLK 256

// ---------------- scratch ----------------
__device__ float g_h1[(size_t)N1C * D];
__device__ __nv_bfloat16 g_Aexp[(size_t)N1C * KSTORE];   // 81.9 MB (reused layer 2)
__device__ __nv_bfloat16 g_Wb1[(size_t)D * KEXP];
__device__ __nv_bfloat16 g_Wb2[(size_t)D * KEXP];
__device__ int g_hist[N1C];          // zero at steady state (self-cleaning)
__device__ int g_off[N1C];
__device__ int g_cur[N1C];
__device__ int g_ssrc[E1MAX];
__device__ int g_counter[1];         // zero at steady state (self-cleaning)

// ---------------- helpers ----------------
__device__ __forceinline__ uint32_t smem_u32(const void* p) {
    uint32_t a;
    asm("{ .reg .u64 t; cvta.to.shared.u64 t, %1; cvt.u32.u64 %0, t; }"
        : "=r"(a) : "l"(p));
    return a;
}
#define SWZ(o) ((o) ^ (((o) >> 3) & 0x70))

__device__ __forceinline__ void cp_async16(uint32_t dst, const void* src) {
    asm volatile("cp.async.cg.shared.global [%0], [%1], 16;" :: "r"(dst), "l"(src));
}
#define CP_COMMIT()  asm volatile("cp.async.commit_group;")
#define CP_WAIT(n)   asm volatile("cp.async.wait_group %0;" :: "n"(n))

__device__ __forceinline__ void ldsm_x4(uint32_t& r0, uint32_t& r1,
                                        uint32_t& r2, uint32_t& r3, uint32_t addr) {
    asm volatile("ldmatrix.sync.aligned.m8n8.x4.shared.b16 {%0,%1,%2,%3}, [%4];"
                 : "=r"(r0), "=r"(r1), "=r"(r2), "=r"(r3) : "r"(addr));
}
__device__ __forceinline__ void mma_bf16(float* c,
        uint32_t a0, uint32_t a1, uint32_t a2, uint32_t a3,
        uint32_t b0, uint32_t b1) {
    asm volatile(
        "mma.sync.aligned.m16n8k16.row.col.f32.bf16.bf16.f32 "
        "{%0,%1,%2,%3}, {%4,%5,%6,%7}, {%8,%9}, {%0,%1,%2,%3};"
        : "+f"(c[0]), "+f"(c[1]), "+f"(c[2]), "+f"(c[3])
        : "r"(a0), "r"(a1), "r"(a2), "r"(a3), "r"(b0), "r"(b1));
}

// ---------------- sort-by-dst pipeline (node-minimized) ----------------
__global__ void hist_kernel(const int* __restrict__ dst, int E, int* __restrict__ hist) {
    int i = blockIdx.x * blockDim.x + threadIdx.x;
    if (i < E) atomicAdd(hist + dst[i], 1);
}

// Single-kernel unordered partition: block-local inclusive scan + atomic base.
// Segments need not be monotone in d; agg uses end=cur[d] after binning.
// Self-cleaning: zeroes hist after reading it.
__global__ void alloc_kernel(int* __restrict__ hist, int* __restrict__ off,
                             int* __restrict__ cur, int* __restrict__ counter, int n) {
    __shared__ int sh[SCAN_BLK];
    __shared__ int base;
    const int t = threadIdx.x;
    const int i = blockIdx.x * SCAN_BLK + t;
    const int v = (i < n) ? hist[i] : 0;
    sh[t] = v;
    __syncthreads();
    #pragma unroll
    for (int d = 1; d < SCAN_BLK; d <<= 1) {
        int u = (t >= d) ? sh[t - d] : 0;
        __syncthreads();
        sh[t] += u;
        __syncthreads();
    }
    if (t == SCAN_BLK - 1) base = atomicAdd(counter, sh[SCAN_BLK - 1]);
    __syncthreads();
    const int o = base + sh[t] - v;   // exclusive within block + global base
    if (i < n) { off[i] = o; cur[i] = o; hist[i] = 0; }
}

// bin: place src into its dst segment; also resets the alloc counter (consumed).
__global__ void bin_kernel(const int* __restrict__ src, const int* __restrict__ dst,
                           int E, int* __restrict__ cur, int* __restrict__ ssrc,
                           int* __restrict__ counter) {
    int i = blockIdx.x * blockDim.x + threadIdx.x;
    if (i == 0) counter[0] = 0;
    if (i >= E) return;
    int p = atomicAdd(cur + dst[i], 1);
    ssrc[p] = src[i];
}

// ---------------- fused aggregation + mean + bf16-split prep ----------------
// warp per dst node; Aexp row: [0:256)=hi(mean) [256:512)=hi(x) [512:768)=lo(mean) [768:1024)=lo(x)
__device__ __forceinline__ void split4(float4 v, ushort4& hi, ushort4& lo) {
    float f[4] = {v.x, v.y, v.z, v.w};
    unsigned short* hp = &hi.x;
    unsigned short* lp = &lo.x;
    #pragma unroll
    for (int t = 0; t < 4; t++) {
        __nv_bfloat16 h = __float2bfloat16(f[t]);
        __nv_bfloat16 l = __float2bfloat16(f[t] - __bfloat162float(h));
        hp[t] = *(unsigned short*)&h;
        lp[t] = *(unsigned short*)&l;
    }
}
__device__ __forceinline__ void acc4(float4& a, float4 v) {
    a.x += v.x; a.y += v.y; a.z += v.z; a.w += v.w;
}

__global__ void agg_prep_kernel(const float* __restrict__ x,
                                const int* __restrict__ off,
                                const int* __restrict__ cur,
                                const int* __restrict__ ssrc,
                                __nv_bfloat16* __restrict__ Aexp, int n) {
    const int d = (blockIdx.x * blockDim.x + threadIdx.x) >> 5;
    const int lane = threadIdx.x & 31;
    if (d >= n) return;
    const int beg = __ldg(off + d);
    const int end = __ldg(cur + d);      // after bin: off[d] + degree(d)

    float4 a0 = make_float4(0, 0, 0, 0), a1 = make_float4(0, 0, 0, 0);
    int e = beg;
    for (; e + 4 <= end; e += 4) {
        int s0 = __ldg(ssrc + e + 0);
        int s1 = __ldg(ssrc + e + 1);
        int s2 = __ldg(ssrc + e + 2);
        int s3 = __ldg(ssrc + e + 3);
        const float4* p0 = (const float4*)(x + (size_t)s0 * D);
        const float4* p1 = (const float4*)(x + (size_t)s1 * D);
        const float4* p2 = (const float4*)(x + (size_t)s2 * D);
        const float4* p3 = (const float4*)(x + (size_t)s3 * D);
        float4 u00 = __ldg(p0 + lane),      u01 = __ldg(p0 + lane + 32);
        float4 u10 = __ldg(p1 + lane),      u11 = __ldg(p1 + lane + 32);
        float4 u20 = __ldg(p2 + lane),      u21 = __ldg(p2 + lane + 32);
        float4 u30 = __ldg(p3 + lane),      u31 = __ldg(p3 + lane + 32);
        acc4(a0, u00); acc4(a1, u01);
        acc4(a0, u10); acc4(a1, u11);
        acc4(a0, u20); acc4(a1, u21);
        acc4(a0, u30); acc4(a1, u31);
    }
    for (; e < end; e++) {
        int s = __ldg(ssrc + e);
        const float4* p = (const float4*)(x + (size_t)s * D);
        acc4(a0, __ldg(p + lane));
        acc4(a1, __ldg(p + lane + 32));
    }

    const float inv = 1.0f / fmaxf((float)(end - beg), 1.0f);
    a0.x *= inv; a0.y *= inv; a0.z *= inv; a0.w *= inv;
    a1.x *= inv; a1.y *= inv; a1.z *= inv; a1.w *= inv;

    const float4* pt = (const float4*)(x + (size_t)d * D);
    float4 t0 = __ldg(pt + lane), t1 = __ldg(pt + lane + 32);

    ushort4 h, l;
    __nv_bfloat16* row = Aexp + (size_t)d * KSTORE;
    split4(a0, h, l);
    *(ushort4*)(row +   0 + 4 * lane) = h;  *(ushort4*)(row + 512 + 4 * lane) = l;
    split4(a1, h, l);
    *(ushort4*)(row + 128 + 4 * lane) = h;  *(ushort4*)(row + 640 + 4 * lane) = l;
    split4(t0, h, l);
    *(ushort4*)(row + 256 + 4 * lane) = h;  *(ushort4*)(row + 768 + 4 * lane) = l;
    split4(t1, h, l);
    *(ushort4*)(row + 384 + 4 * lane) = h;  *(ushort4*)(row + 896 + 4 * lane) = l;
}

// ---------------- weight prep (both layers in one launch) ----------------
__global__ void wprep2_kernel(const float* __restrict__ Wl1, const float* __restrict__ Wr1,
                              __nv_bfloat16* __restrict__ Wb1,
                              const float* __restrict__ Wl2, const float* __restrict__ Wr2,
                              __nv_bfloat16* __restrict__ Wb2) {
    int i = blockIdx.x * blockDim.x + threadIdx.x;
    if (i >= 2 * D * 512) return;
    const float* Wl = (i < D * 512) ? Wl1 : Wl2;
    const float* Wr = (i < D * 512) ? Wr1 : Wr2;
    __nv_bfloat16* Wb = (i < D * 512) ? Wb1 : Wb2;
    int j = (i < D * 512) ? i : (i - D * 512);
    int n = j / 512, k = j % 512;
    float w = (k < D) ? Wl[n * D + k] : Wr[n * D + (k - D)];
    __nv_bfloat16 hi = __float2bfloat16(w);
    __nv_bfloat16 lo = __float2bfloat16(w - __bfloat162float(hi));
    __nv_bfloat16* row = Wb + (size_t)n * KEXP;
    row[k]        = hi;
    row[512 + k]  = lo;
    row[1024 + k] = hi;
}

// ---------------- mma.sync bf16 GEMM (R7-proven, unchanged) ----------------
__global__ __launch_bounds__(256, 1)
void sage_mma_gemm(const __nv_bfloat16* __restrict__ Aexp,
                   const __nv_bfloat16* __restrict__ Wb,
                   const float* __restrict__ bias,
                   float* __restrict__ out, int M) {
    extern __shared__ __align__(1024) char smem[];
    const uint32_t TILES = (smem_u32(smem) + 1023u) & ~1023u;

    const int tid  = threadIdx.x;
    const int wid  = tid >> 5;
    const int lane = tid & 31;
    const int wm   = wid & 3;
    const int wn   = wid >> 2;
    const int row0 = blockIdx.x * BM;
    const int col0 = blockIdx.y * BN;

    const int ld_r = tid >> 3;
    const int ld_q = tid & 7;

    uint32_t aPart[2], bPart[4];
    {
        int r  = (lane & 15);
        int hb = (lane >> 4) * 16;
        #pragma unroll
        for (int mi = 0; mi < 2; mi++)
            aPart[mi] = (uint32_t)((wm * 32 + mi * 16 + r) * 128 + hb);
        #pragma unroll
        for (int g = 0; g < 4; g++)
            bPart[g] = (uint32_t)((wn * 64 + g * 16 + r) * 128 + hb);
    }

    float acc[2][8][4];
    #pragma unroll
    for (int mi = 0; mi < 2; mi++)
        #pragma unroll
        for (int ni = 0; ni < 8; ni++)
            #pragma unroll
            for (int t = 0; t < 4; t++) acc[mi][ni][t] = 0.0f;

    auto load_chunk = [&](int c) {
        const int s  = c % STAGES;
        const int kb = c * KC;
        const int ka = (kb < 512) ? kb : kb - 512;
        const uint32_t sA = TILES + s * STAGE_BYTES;
        const uint32_t sB = sA + BM * 128;
        #pragma unroll
        for (int i = 0; i < 4; i++) {
            int m = ld_r + i * 32;
            int gr = row0 + m; if (gr > M - 1) gr = M - 1;
            cp_async16(sA + SWZ(m * 128 + ld_q * 16),
                       Aexp + (size_t)gr * KSTORE + ka + ld_q * 8);
        }
        #pragma unroll
        for (int i = 0; i < 4; i++) {
            int n = ld_r + i * 32;
            cp_async16(sB + SWZ(n * 128 + ld_q * 16),
                       Wb + (size_t)(col0 + n) * KEXP + kb + ld_q * 8);
        }
        CP_COMMIT();
    };

    load_chunk(0);
    load_chunk(1);

    #pragma unroll 1
    for (int c = 0; c < NCHUNK; c++) {
        if (c == NCHUNK - 1) { CP_WAIT(0); } else { CP_WAIT(1); }
        __syncthreads();
        if (c + 2 < NCHUNK) load_chunk(c + 2);

        const uint32_t sA = TILES + (c % STAGES) * STAGE_BYTES;
        const uint32_t sB = sA + BM * 128;

        #pragma unroll
        for (int ks = 0; ks < 4; ks++) {
            const uint32_t kadv = ks * 32;
            uint32_t a[2][4];
            #pragma unroll
            for (int mi = 0; mi < 2; mi++)
                ldsm_x4(a[mi][0], a[mi][1], a[mi][2], a[mi][3],
                        sA + SWZ(aPart[mi] + kadv));
            uint32_t b[8][2];
            #pragma unroll
            for (int g = 0; g < 4; g++) {
                uint32_t r0, r1, r2, r3;
                ldsm_x4(r0, r1, r2, r3, sB + SWZ(bPart[g] + kadv));
                b[2*g][0] = r0;  b[2*g+1][0] = r1;
                b[2*g][1] = r2;  b[2*g+1][1] = r3;
            }
            #pragma unroll
            for (int mi = 0; mi < 2; mi++)
                #pragma unroll
                for (int ni = 0; ni < 8; ni++)
                    mma_bf16(acc[mi][ni],
                             a[mi][0], a[mi][1], a[mi][2], a[mi][3],
                             b[ni][0], b[ni][1]);
        }
    }

    const int rbase = row0 + wm * 32 + (lane >> 2);
    const int cbase = col0 + wn * 64 + 2 * (lane & 3);
    #pragma unroll
    for (int ni = 0; ni < 8; ni++) {
        const int col = cbase + ni * 8;
        const float2 bv = *(const float2*)(bias + col);
        #pragma unroll
        for (int mi = 0; mi < 2; mi++) {
            int r = rbase + mi * 16;
            if (r < M) {
                float2 o;
                o.x = tanhf(acc[mi][ni][0] + bv.x);
                o.y = tanhf(acc[mi][ni][1] + bv.y);
                *(float2*)(out + (size_t)r * D + col) = o;
            }
            if (r + 8 < M) {
                float2 o;
                o.x = tanhf(acc[mi][ni][2] + bv.x);
                o.y = tanhf(acc[mi][ni][3] + bv.y);
                *(float2*)(out + (size_t)(r + 8) * D + col) = o;
            }
        }
    }
}

// ---------------- launch ----------------
extern "C" void kernel_launch(void* const* d_in, const int* in_sizes, int n_in,
                              void* d_out, int out_size) {
    const float* nodes = (const float*)d_in[0];
    const float* Wl1   = (const float*)d_in[1];
    const float* b1    = (const float*)d_in[2];
    const float* Wr1   = (const float*)d_in[3];
    const float* Wl2   = (const float*)d_in[4];
    const float* b2    = (const float*)d_in[5];
    const float* Wr2   = (const float*)d_in[6];
    const int*   src1  = (const int*)d_in[7];
    const int*   dst1  = (const int*)d_in[8];
    const int*   src2  = (const int*)d_in[9];
    const int*   dst2  = (const int*)d_in[10];
    const int E1 = in_sizes[7];
    const int E2 = in_sizes[9];

    float *p_h1;
    __nv_bfloat16 *p_Aexp, *p_Wb1, *p_Wb2;
    int *p_hist, *p_off, *p_cur, *p_ssrc, *p_counter;
    cudaGetSymbolAddress((void**)&p_h1,      g_h1);
    cudaGetSymbolAddress((void**)&p_Aexp,    g_Aexp);
    cudaGetSymbolAddress((void**)&p_Wb1,     g_Wb1);
    cudaGetSymbolAddress((void**)&p_Wb2,     g_Wb2);
    cudaGetSymbolAddress((void**)&p_hist,    g_hist);
    cudaGetSymbolAddress((void**)&p_off,     g_off);
    cudaGetSymbolAddress((void**)&p_cur,     g_cur);
    cudaGetSymbolAddress((void**)&p_ssrc,    g_ssrc);
    cudaGetSymbolAddress((void**)&p_counter, g_counter);

    cudaFuncSetAttribute(sage_mma_gemm, cudaFuncAttributeMaxDynamicSharedMemorySize,
                         SMEM_BYTES);

    wprep2_kernel<<<(2 * D * 512 + 255) / 256, 256>>>(Wl1, Wr1, p_Wb1, Wl2, Wr2, p_Wb2);

    // ---- layer 1 ----  (hist/counter are zero at entry: self-cleaning invariant)
    {
        const int nb = (N1C + SCAN_BLK - 1) / SCAN_BLK;
        hist_kernel<<<(E1 + 255) / 256, 256>>>(dst1, E1, p_hist);
        alloc_kernel<<<nb, SCAN_BLK>>>(p_hist, p_off, p_cur, p_counter, N1C);
        bin_kernel<<<(E1 + 255) / 256, 256>>>(src1, dst1, E1, p_cur, p_ssrc, p_counter);
        agg_prep_kernel<<<(N1C * 32 + 255) / 256, 256>>>(nodes, p_off, p_cur, p_ssrc,
                                                         p_Aexp, N1C);
        dim3 grid((N1C + BM - 1) / BM, D / BN);
        sage_mma_gemm<<<grid, 256, SMEM_BYTES>>>(p_Aexp, p_Wb1, b1, p_h1, N1C);
    }

    // ---- layer 2 ----
    {
        const int nb = (N2C + SCAN_BLK - 1) / SCAN_BLK;
        hist_kernel<<<(E2 + 255) / 256, 256>>>(dst2, E2, p_hist);
        alloc_kernel<<<nb, SCAN_BLK>>>(p_hist, p_off, p_cur, p_counter, N2C);
        bin_kernel<<<(E2 + 255) / 256, 256>>>(src2, dst2, E2, p_cur, p_ssrc, p_counter);
        agg_prep_kernel<<<(N2C * 32 + 255) / 256, 256>>>(p_h1, p_off, p_cur, p_ssrc,
                                                         p_Aexp, N2C);
        dim3 grid((N2C + BM - 1) / BM, D / BN);
        sage_mma_gemm<<<grid, 256, SMEM_BYTES>>>(p_Aexp, p_Wb2, b2, (float*)d_out, N2C);
    }
}